// round 5
// baseline (speedup 1.0000x reference)
#include <cuda_runtime.h>

// Problem constants
static constexpr int   N_PTS   = 16384;
static constexpr int   C_DIM   = 16;
static constexpr int   H_DIM   = 32;
static constexpr int   KNN     = 9;
static constexpr float UPD_RATE = 1e-4f;

// Spatial grid: 128x128 over [-5,5]; ~16 pts/cell at Gaussian peak.
static constexpr int   GG  = 128;
static constexpr float GB  = 5.0f;
static constexpr int   CAP = 64;
static constexpr float CS  = 2.0f * GB / GG;     // 0.078125
static constexpr float INV_CS = GG / (2.0f * GB);

// Persistent-kernel shape: one 1024-thread block per SM (co-resident wave 1).
static constexpr int NBLK = 148;
static constexpr int NTHR = 1024;
static constexpr int NTOT = NBLK * NTHR;   // 151552 threads
static constexpr int NWRP = NTOT / 32;     // 4736 warps

// Scratch (device globals: allocation-free per harness rules)
__device__ __align__(16) float  g_x [N_PTS * C_DIM];
__device__ __align__(16) float  g_ha[N_PTS * H_DIM];
__device__ __align__(16) float  g_hb[N_PTS * H_DIM];
__device__ int    g_idx[N_PTS * KNN];
__device__ int    g_cnt[GG * GG];
__device__ float4 g_pts[GG * GG * CAP];    // (x, y, bitcast(id), 0)

// Grid barrier state (sense persists across graph replays; read at start).
__device__ int      g_bar_count = 0;
__device__ unsigned g_bar_sense = 0;

__device__ __forceinline__ void gsync(unsigned& sense) {
    __threadfence();                  // release: every thread's prior writes
    __syncthreads();
    ++sense;
    if (threadIdx.x == 0) {
        int v = atomicAdd(&g_bar_count, 1);
        if (v == NBLK - 1) {
            g_bar_count = 0;
            __threadfence();
            atomicExch(&g_bar_sense, sense);
        } else {
            while (*((volatile unsigned*)&g_bar_sense) != sense) __nanosleep(32);
        }
        __threadfence();              // acquire side
    }
    __syncthreads();
}

__device__ __forceinline__ int cell_coord(float v) {
    int c = (int)floorf((v + GB) * INV_CS);
    c = c < 0 ? 0 : c;
    c = c > GG - 1 ? GG - 1 : c;
    return c;
}

__device__ __forceinline__ void bin_insert(float px, float py, int id) {
    int b = cell_coord(py) * GG + cell_coord(px);
    int s = atomicAdd(&g_cnt[b], 1);
    if (s < CAP) g_pts[b * CAP + s] = make_float4(px, py, __int_as_float(id), 0.0f);
}

// ---------------------------------------------------------------------------
// Warp-per-query kNN; each lane scans its assigned ring cell PRIVATELY
// (no intra-scan warp coordination). Per-lane sorted top-9; warp-count
// termination per ring; final u64 min-reduce merge.
__device__ __forceinline__ void knn_query(int q, int lane) {
    const float qx = g_x[q * C_DIM + 0];
    const float qy = g_x[q * C_DIM + 1];
    const int cx = cell_coord(qx);
    const int cy = cell_coord(qy);

    const float INF = __int_as_float(0x7f800000);
    float bd[KNN];
    int   bi[KNN];
#pragma unroll
    for (int p = 0; p < KNN; ++p) { bd[p] = INF; bi[p] = q; }

    auto insert_pt = [&](float d2, int id) {
        if (d2 < bd[KNN - 1]) {
            float cd = d2;
            int   ci = id;
#pragma unroll
            for (int pos = 0; pos < KNN; ++pos) {
                if (cd < bd[pos]) {
                    float tf = bd[pos]; bd[pos] = cd; cd = tf;
                    int   ti = bi[pos]; bi[pos] = ci; ci = ti;
                }
            }
        }
    };

    {   // r = 0: all lanes cooperate on the (usually dense) center cell
        int b = cy * GG + cx;
        int cnt = g_cnt[b];
        cnt = cnt < CAP ? cnt : CAP;
        const float4* pp = &g_pts[b * CAP];
        for (int t = lane; t < cnt; t += 32) {
            float4 p = pp[t];
            float dx = qx - p.x;
            float dy = qy - p.y;
            insert_pt(__fadd_rn(__fmul_rn(dx, dx), __fmul_rn(dy, dy)),
                      __float_as_int(p.z));
        }
    }

    for (int r = 1; r < GG; ++r) {
        int nc = 8 * r;
        for (int base = 0; base < nc; base += 32) {
            int i = base + lane;
            if (i < nc) {
                int xx, yy;
                int side = 2 * r + 1;
                if (i < side)          { xx = cx - r + i;          yy = cy - r; }
                else if (i < 2 * side) { xx = cx - r + (i - side); yy = cy + r; }
                else {
                    int j = i - 2 * side;
                    int m = 2 * r - 1;
                    xx = (j < m) ? (cx - r) : (cx + r);
                    yy = cy - r + 1 + (j < m ? j : j - m);
                }
                if (xx >= 0 && xx < GG && yy >= 0 && yy < GG) {
                    int b = yy * GG + xx;
                    int cnt = g_cnt[b];
                    cnt = cnt < CAP ? cnt : CAP;
                    const float4* pp = &g_pts[b * CAP];
                    for (int t = 0; t < cnt; ++t) {
                        float4 p = pp[t];
                        float dx = qx - p.x;
                        float dy = qy - p.y;
                        insert_pt(__fadd_rn(__fmul_rn(dx, dx), __fmul_rn(dy, dy)),
                                  __float_as_int(p.z));
                    }
                }
            }
        }
        // >= KNN warp-wide candidates within rim = r*CS  =>  safe to stop
        // (unvisited cells are all at distance >= r*CS).
        float rim = (float)r * CS;
        float rim2 = rim * rim;
        int c = 0;
#pragma unroll
        for (int p = 0; p < KNN; ++p) c += (bd[p] <= rim2) ? 1 : 0;
#pragma unroll
        for (int off = 16; off > 0; off >>= 1)
            c += __shfl_xor_sync(0xffffffffu, c, off);
        if (c >= KNN) break;
    }

    // Merge 32 sorted local lists -> global top-9.
#pragma unroll
    for (int sel = 0; sel < KNN; ++sel) {
        unsigned long long pack =
            ((unsigned long long)__float_as_uint(bd[0]) << 32) | (unsigned)bi[0];
        unsigned long long m = pack;
#pragma unroll
        for (int off = 16; off > 0; off >>= 1) {
            unsigned long long o = __shfl_xor_sync(0xffffffffu, m, off);
            m = o < m ? o : m;
        }
        unsigned matched = __ballot_sync(0xffffffffu, pack == m);
        if (lane == __ffs(matched) - 1) {
#pragma unroll
            for (int p = 0; p < KNN - 1; ++p) { bd[p] = bd[p + 1]; bi[p] = bi[p + 1]; }
            bd[KNN - 1] = INF;
            bi[KNN - 1] = q;
        }
        if (lane == 0) g_idx[q * KNN + sel] = (int)(unsigned)(m & 0xffffffffu);
    }
}

// ---------------------------------------------------------------------------
// GCN layer: 4 sub-threads per node. Each gathers CIN/4 channels of the 9
// neighbors, allgathers agg across the 4 lanes (shfl_xor 1,2; static reg
// indexing), then computes its contiguous COUT/4 output slice.
template <int CIN, int COUT, bool RELU, bool UPD, bool ZERO, bool BINFILL, bool WOUT>
__device__ __forceinline__ void layer_phase(const float* __restrict__ hin,
                                            const float* __restrict__ sW,
                                            float* __restrict__ hout,
                                            float* __restrict__ out2,
                                            int gtid) {
    constexpr int CPT = CIN / 4;
    constexpr int QTR = COUT / 4;

    if (ZERO) {
        for (int i = gtid; i < GG * GG; i += NTOT) g_cnt[i] = 0;
    }

    int u = gtid;
    if (u >= N_PTS * 4) return;     // 65536 units; warp-aligned cut
    int n   = u >> 2;
    int sub = u & 3;

    float a0[CPT];
#pragma unroll
    for (int c = 0; c < CPT; ++c) a0[c] = 0.0f;

    const int* ip = g_idx + n * KNN;
#pragma unroll
    for (int k = 0; k < KNN; ++k) {
        int nb = __ldg(&ip[k]);
        const float4* row = (const float4*)(hin + nb * CIN + sub * CPT);
#pragma unroll
        for (int c4 = 0; c4 < CPT / 4; ++c4) {
            float4 v = row[c4];
            a0[4 * c4 + 0] += v.x;
            a0[4 * c4 + 1] += v.y;
            a0[4 * c4 + 2] += v.z;
            a0[4 * c4 + 3] += v.w;
        }
    }
#pragma unroll
    for (int c = 0; c < CPT; ++c) a0[c] *= (1.0f / 9.0f);

    // Allgather agg across the 4 sub-threads.
    bool b0 = (sub & 1) != 0;
    bool b1 = (sub & 2) != 0;
    float a1[2 * CPT];
#pragma unroll
    for (int j = 0; j < CPT; ++j) {
        float rv = __shfl_xor_sync(0xffffffffu, a0[j], 1);
        a1[j]       = b0 ? rv    : a0[j];
        a1[CPT + j] = b0 ? a0[j] : rv;
    }
    float full[CIN];
#pragma unroll
    for (int j = 0; j < 2 * CPT; ++j) {
        float rv = __shfl_xor_sync(0xffffffffu, a1[j], 2);
        full[j]           = b1 ? rv    : a1[j];
        full[2 * CPT + j] = b1 ? a1[j] : rv;
    }

    // My contiguous output quarter.
    int jbase = sub * QTR;
    float acc[QTR];
#pragma unroll
    for (int j = 0; j < QTR; ++j) acc[j] = 0.0f;
#pragma unroll
    for (int c = 0; c < CIN; ++c) {
        float a = full[c];
        const float* wrow = &sW[c * COUT + jbase];
#pragma unroll
        for (int j = 0; j < QTR; ++j) acc[j] = fmaf(a, wrow[j], acc[j]);
    }

    float* outp = hout + n * COUT + jbase;
    float nx = 0.0f, ny = 0.0f;
#pragma unroll
    for (int v4 = 0; v4 < QTR / 4; ++v4) {
        float4 r;
        r.x = acc[4 * v4 + 0];
        r.y = acc[4 * v4 + 1];
        r.z = acc[4 * v4 + 2];
        r.w = acc[4 * v4 + 3];
        if (RELU) {
            r.x = fmaxf(r.x, 0.0f); r.y = fmaxf(r.y, 0.0f);
            r.z = fmaxf(r.z, 0.0f); r.w = fmaxf(r.w, 0.0f);
        }
        if (UPD) {
            float4 old = ((const float4*)outp)[v4];
            r.x = fmaf(r.x, UPD_RATE, old.x);
            r.y = fmaf(r.y, UPD_RATE, old.y);
            r.z = fmaf(r.z, UPD_RATE, old.z);
            r.w = fmaf(r.w, UPD_RATE, old.w);
        }
        ((float4*)outp)[v4] = r;
        if (WOUT) ((float4*)(out2 + n * COUT + jbase))[v4] = r;
        if (BINFILL && v4 == 0 && sub == 0) { nx = r.x; ny = r.y; }
    }
    if (BINFILL && sub == 0) bin_insert(nx, ny, n);
}

// ---------------------------------------------------------------------------
__global__ void __launch_bounds__(NTHR, 1)
k_fused(const float* __restrict__ seed,
        const float* __restrict__ W1, const float* __restrict__ W2,
        const float* __restrict__ W3, const float* __restrict__ W4,
        float* __restrict__ out) {
    __shared__ float sW1[C_DIM * H_DIM];
    __shared__ float sW2[H_DIM * H_DIM];
    __shared__ float sW3[H_DIM * H_DIM];
    __shared__ float sW4[H_DIM * C_DIM];

    const int tid  = threadIdx.x;
    const int gtid = blockIdx.x * NTHR + tid;
    const int gw   = gtid >> 5;
    const int lane = gtid & 31;

    unsigned sense = *((volatile unsigned*)&g_bar_sense);

    // -- init: stage weights, copy seed, zero counters ---------------------
    for (int i = tid; i < C_DIM * H_DIM; i += NTHR) sW1[i] = W1[i];
    for (int i = tid; i < H_DIM * H_DIM; i += NTHR) sW2[i] = W2[i];
    for (int i = tid; i < H_DIM * H_DIM; i += NTHR) sW3[i] = W3[i];
    for (int i = tid; i < H_DIM * C_DIM; i += NTHR) sW4[i] = W4[i];
    {
        const float4* s4 = (const float4*)seed;
        float4*       x4 = (float4*)g_x;
        for (int i = gtid; i < (N_PTS * C_DIM) / 4; i += NTOT) x4[i] = s4[i];
        for (int i = gtid; i < GG * GG; i += NTOT) g_cnt[i] = 0;
    }
    gsync(sense);

    // -- step 0: binfill ----------------------------------------------------
    for (int i = gtid; i < N_PTS; i += NTOT)
        bin_insert(g_x[i * C_DIM + 0], g_x[i * C_DIM + 1], i);
    gsync(sense);

    // -- step 0: knn ----------------------------------------------------------
    for (int q = gw; q < N_PTS; q += NWRP) knn_query(q, lane);
    gsync(sense);

    // -- step 0: layers -------------------------------------------------------
    layer_phase<16, 32, true,  false, false, false, false>(g_x,  sW1, g_ha, nullptr, gtid);
    gsync(sense);
    layer_phase<32, 32, true,  false, false, false, false>(g_ha, sW2, g_hb, nullptr, gtid);
    gsync(sense);
    layer_phase<32, 32, true,  false, true,  false, false>(g_hb, sW3, g_ha, nullptr, gtid); // + zero cnt
    gsync(sense);
    layer_phase<32, 16, false, true,  false, true,  false>(g_ha, sW4, g_x,  nullptr, gtid); // x+=, rebin
    gsync(sense);

    // -- step 1: knn ----------------------------------------------------------
    for (int q = gw; q < N_PTS; q += NWRP) knn_query(q, lane);
    gsync(sense);

    // -- step 1: layers -------------------------------------------------------
    layer_phase<16, 32, true,  false, false, false, false>(g_x,  sW1, g_ha, nullptr, gtid);
    gsync(sense);
    layer_phase<32, 32, true,  false, false, false, false>(g_ha, sW2, g_hb, nullptr, gtid);
    gsync(sense);
    layer_phase<32, 32, true,  false, false, false, false>(g_hb, sW3, g_ha, nullptr, gtid);
    gsync(sense);
    layer_phase<32, 16, false, true,  false, false, true >(g_ha, sW4, g_x,  out, gtid);     // x+=, writeout
}

// ---------------------------------------------------------------------------
extern "C" void kernel_launch(void* const* d_in, const int* in_sizes, int n_in,
                              void* d_out, int out_size) {
    const float* seed = (const float*)d_in[0];
    const float* W1   = (const float*)d_in[1];
    const float* W2   = (const float*)d_in[2];
    const float* W3   = (const float*)d_in[3];
    const float* W4   = (const float*)d_in[4];

    k_fused<<<NBLK, NTHR>>>(seed, W1, W2, W3, W4, (float*)d_out);
}

// round 6
// speedup vs baseline: 1.0604x; 1.0604x over previous
#include <cuda_runtime.h>

// Problem constants
static constexpr int   N_PTS   = 16384;
static constexpr int   C_DIM   = 16;
static constexpr int   H_DIM   = 32;
static constexpr int   KNN     = 9;
static constexpr float UPD_RATE = 1e-4f;

// Spatial grid: 128x128 over [-5,5]; ~16 pts/cell at Gaussian peak.
static constexpr int   GG  = 128;
static constexpr float GB  = 5.0f;
static constexpr int   CAP = 64;
static constexpr float CS  = 2.0f * GB / GG;     // 0.078125
static constexpr float INV_CS = GG / (2.0f * GB);
static constexpr int   NCELL = GG * GG;          // 16384

// Persistent-kernel shape: one 1024-thread block per SM (co-resident wave 1).
static constexpr int NBLK = 148;
static constexpr int NTHR = 1024;
static constexpr int NTOT = NBLK * NTHR;   // 151552 threads
static constexpr int NWRP = NTOT / 32;     // 4736 warps

// Scratch (device globals: allocation-free per harness rules)
__device__ __align__(16) float  g_x [N_PTS * C_DIM];
__device__ __align__(16) float  g_ha[N_PTS * H_DIM];
__device__ __align__(16) float  g_hb[N_PTS * H_DIM];
__device__ int    g_idx[N_PTS * KNN];
__device__ int    g_cnt[NCELL];
__device__ float4 g_pts[NCELL * CAP];      // (x, y, bitcast(id), 0)

// Grid barrier state (sense persists across graph replays; read at start).
__device__ int      g_bar_count = 0;
__device__ unsigned g_bar_sense = 0;

__device__ __forceinline__ void gsync(unsigned& sense) {
    __threadfence();
    __syncthreads();
    ++sense;
    if (threadIdx.x == 0) {
        int v = atomicAdd(&g_bar_count, 1);
        if (v == NBLK - 1) {
            g_bar_count = 0;
            __threadfence();
            atomicExch(&g_bar_sense, sense);
        } else {
            while (*((volatile unsigned*)&g_bar_sense) != sense) __nanosleep(32);
        }
        __threadfence();
    }
    __syncthreads();
}

__device__ __forceinline__ int cell_coord(float v) {
    int c = (int)floorf((v + GB) * INV_CS);
    c = c < 0 ? 0 : c;
    c = c > GG - 1 ? GG - 1 : c;
    return c;
}

__device__ __forceinline__ void bin_insert(float px, float py, int id) {
    int b = cell_coord(py) * GG + cell_coord(px);
    int s = atomicAdd(&g_cnt[b], 1);
    if (s < CAP) g_pts[b * CAP + s] = make_float4(px, py, __int_as_float(id), 0.0f);
}

// ---------------------------------------------------------------------------
// Cell-centric kNN: one warp per grid cell; lane = resident query point.
// Ring-cell counts probed 32-wide; each non-empty cell's points streamed
// once via broadcast loads; every lane keeps a private sorted top-9 and
// writes its own query's result. Exact per-query box termination.
__device__ __forceinline__ void knn_cell(int cell, int lane) {
    int qcnt = g_cnt[cell];
    qcnt = qcnt < CAP ? qcnt : CAP;
    if (qcnt == 0) return;

    const int cx = cell & (GG - 1);
    const int cy = cell >> 7;            // GG == 128

    const float INF = __int_as_float(0x7f800000);

    for (int qb = 0; qb < qcnt; qb += 32) {
        int  qi  = qb + lane;
        bool has = (qi < qcnt);
        float4 qp = has ? g_pts[cell * CAP + qi]
                        : make_float4(1e38f, 1e38f, __int_as_float(0), 0.0f);
        const float qx = qp.x;
        const float qy = qp.y;
        const int   q  = __float_as_int(qp.z);

        float bd[KNN];
        int   bi[KNN];
#pragma unroll
        for (int p = 0; p < KNN; ++p) { bd[p] = INF; bi[p] = q; }

        auto stream_cell = [&](int bb, int cc) {
            const float4* pp = &g_pts[bb * CAP];
            for (int t = 0; t < cc; ++t) {
                float4 p = pp[t];                      // broadcast load
                float dx = qx - p.x;
                float dy = qy - p.y;
                float d2 = __fadd_rn(__fmul_rn(dx, dx), __fmul_rn(dy, dy));
                if (d2 < bd[KNN - 1]) {
                    float cd = d2;
                    int   ci = __float_as_int(p.z);
#pragma unroll
                    for (int pos = 0; pos < KNN; ++pos) {
                        if (cd < bd[pos]) {
                            float tf = bd[pos]; bd[pos] = cd; cd = tf;
                            int   ti = bi[pos]; bi[pos] = ci; ci = ti;
                        }
                    }
                }
            }
        };

        // ring 0: home cell (count already known)
        stream_cell(cell, qcnt);

        for (int r = 1; r < 2 * GG; ++r) {
            int nc = 8 * r;
            for (int base = 0; base < nc; base += 32) {
                int i = base + lane;
                int b2 = 0, c2 = 0;
                if (i < nc) {
                    int xx, yy;
                    int side = 2 * r + 1;
                    if (i < side)          { xx = cx - r + i;          yy = cy - r; }
                    else if (i < 2 * side) { xx = cx - r + (i - side); yy = cy + r; }
                    else {
                        int j = i - 2 * side;
                        int m = 2 * r - 1;
                        xx = (j < m) ? (cx - r) : (cx + r);
                        yy = cy - r + 1 + (j < m ? j : j - m);
                    }
                    if (xx >= 0 && xx < GG && yy >= 0 && yy < GG) {
                        b2 = yy * GG + xx;
                        c2 = g_cnt[b2];
                        c2 = c2 < CAP ? c2 : CAP;
                    }
                }
                unsigned mask = __ballot_sync(0xffffffffu, c2 > 0);
                while (mask) {
                    int s = __ffs(mask) - 1;
                    mask &= mask - 1;
                    int bb = __shfl_sync(0xffffffffu, b2, s);
                    int cc = __shfl_sync(0xffffffffu, c2, s);
                    stream_cell(bb, cc);
                }
            }
            // Exact termination: all unscanned points lie OUTSIDE the box
            // [x_lo,x_hi]x[y_lo,y_hi]; a query inside the box at distance
            // dmin from its boundary is done once bd[8] <= dmin^2.
            float x_lo = -GB + (float)(cx - r) * CS;
            float x_hi = -GB + (float)(cx + r + 1) * CS;
            float y_lo = -GB + (float)(cy - r) * CS;
            float y_hi = -GB + (float)(cy + r + 1) * CS;
            float dmin = fminf(fminf(qx - x_lo, x_hi - qx),
                               fminf(qy - y_lo, y_hi - qy));
            bool done = (!has) || (dmin > 0.0f && bd[KNN - 1] <= dmin * dmin);
            if (__all_sync(0xffffffffu, done)) break;
        }

        if (has) {
#pragma unroll
            for (int p = 0; p < KNN; ++p) g_idx[q * KNN + p] = bi[p];
        }
    }
}

// ---------------------------------------------------------------------------
// GCN layer: 4 sub-threads per node; allgather agg via shfl_xor(1,2);
// each sub-thread computes its contiguous COUT/4 output slice.
template <int CIN, int COUT, bool RELU, bool UPD, bool ZERO, bool BINFILL, bool WOUT>
__device__ __forceinline__ void layer_phase(const float* __restrict__ hin,
                                            const float* __restrict__ sW,
                                            float* __restrict__ hout,
                                            float* __restrict__ out2,
                                            int gtid) {
    constexpr int CPT = CIN / 4;
    constexpr int QTR = COUT / 4;

    if (ZERO) {
        for (int i = gtid; i < NCELL; i += NTOT) g_cnt[i] = 0;
    }

    int u = gtid;
    if (u >= N_PTS * 4) return;
    int n   = u >> 2;
    int sub = u & 3;

    float a0[CPT];
#pragma unroll
    for (int c = 0; c < CPT; ++c) a0[c] = 0.0f;

    const int* ip = g_idx + n * KNN;
#pragma unroll
    for (int k = 0; k < KNN; ++k) {
        int nb = __ldg(&ip[k]);
        const float4* row = (const float4*)(hin + nb * CIN + sub * CPT);
#pragma unroll
        for (int c4 = 0; c4 < CPT / 4; ++c4) {
            float4 v = row[c4];
            a0[4 * c4 + 0] += v.x;
            a0[4 * c4 + 1] += v.y;
            a0[4 * c4 + 2] += v.z;
            a0[4 * c4 + 3] += v.w;
        }
    }
#pragma unroll
    for (int c = 0; c < CPT; ++c) a0[c] *= (1.0f / 9.0f);

    bool b0 = (sub & 1) != 0;
    bool b1 = (sub & 2) != 0;
    float a1[2 * CPT];
#pragma unroll
    for (int j = 0; j < CPT; ++j) {
        float rv = __shfl_xor_sync(0xffffffffu, a0[j], 1);
        a1[j]       = b0 ? rv    : a0[j];
        a1[CPT + j] = b0 ? a0[j] : rv;
    }
    float full[CIN];
#pragma unroll
    for (int j = 0; j < 2 * CPT; ++j) {
        float rv = __shfl_xor_sync(0xffffffffu, a1[j], 2);
        full[j]           = b1 ? rv    : a1[j];
        full[2 * CPT + j] = b1 ? a1[j] : rv;
    }

    int jbase = sub * QTR;
    float acc[QTR];
#pragma unroll
    for (int j = 0; j < QTR; ++j) acc[j] = 0.0f;
#pragma unroll
    for (int c = 0; c < CIN; ++c) {
        float a = full[c];
        const float* wrow = &sW[c * COUT + jbase];
#pragma unroll
        for (int j = 0; j < QTR; ++j) acc[j] = fmaf(a, wrow[j], acc[j]);
    }

    float* outp = hout + n * COUT + jbase;
    float nx = 0.0f, ny = 0.0f;
#pragma unroll
    for (int v4 = 0; v4 < QTR / 4; ++v4) {
        float4 r;
        r.x = acc[4 * v4 + 0];
        r.y = acc[4 * v4 + 1];
        r.z = acc[4 * v4 + 2];
        r.w = acc[4 * v4 + 3];
        if (RELU) {
            r.x = fmaxf(r.x, 0.0f); r.y = fmaxf(r.y, 0.0f);
            r.z = fmaxf(r.z, 0.0f); r.w = fmaxf(r.w, 0.0f);
        }
        if (UPD) {
            float4 old = ((const float4*)outp)[v4];
            r.x = fmaf(r.x, UPD_RATE, old.x);
            r.y = fmaf(r.y, UPD_RATE, old.y);
            r.z = fmaf(r.z, UPD_RATE, old.z);
            r.w = fmaf(r.w, UPD_RATE, old.w);
        }
        ((float4*)outp)[v4] = r;
        if (WOUT) ((float4*)(out2 + n * COUT + jbase))[v4] = r;
        if (BINFILL && v4 == 0 && sub == 0) { nx = r.x; ny = r.y; }
    }
    if (BINFILL && sub == 0) bin_insert(nx, ny, n);
}

// ---------------------------------------------------------------------------
__global__ void __launch_bounds__(NTHR, 1)
k_fused(const float* __restrict__ seed,
        const float* __restrict__ W1, const float* __restrict__ W2,
        const float* __restrict__ W3, const float* __restrict__ W4,
        float* __restrict__ out) {
    __shared__ float sW1[C_DIM * H_DIM];
    __shared__ float sW2[H_DIM * H_DIM];
    __shared__ float sW3[H_DIM * H_DIM];
    __shared__ float sW4[H_DIM * C_DIM];

    const int tid  = threadIdx.x;
    const int gtid = blockIdx.x * NTHR + tid;
    const int gw   = gtid >> 5;
    const int lane = gtid & 31;

    unsigned sense = *((volatile unsigned*)&g_bar_sense);

    // -- init: stage weights, copy seed, zero counters ---------------------
    for (int i = tid; i < C_DIM * H_DIM; i += NTHR) sW1[i] = W1[i];
    for (int i = tid; i < H_DIM * H_DIM; i += NTHR) sW2[i] = W2[i];
    for (int i = tid; i < H_DIM * H_DIM; i += NTHR) sW3[i] = W3[i];
    for (int i = tid; i < H_DIM * C_DIM; i += NTHR) sW4[i] = W4[i];
    {
        const float4* s4 = (const float4*)seed;
        float4*       x4 = (float4*)g_x;
        for (int i = gtid; i < (N_PTS * C_DIM) / 4; i += NTOT) x4[i] = s4[i];
        for (int i = gtid; i < NCELL; i += NTOT) g_cnt[i] = 0;
    }
    gsync(sense);

    // -- step 0: binfill ----------------------------------------------------
    for (int i = gtid; i < N_PTS; i += NTOT)
        bin_insert(g_x[i * C_DIM + 0], g_x[i * C_DIM + 1], i);
    gsync(sense);

    // -- step 0: knn (warp per cell) ------------------------------------------
    for (int c = gw; c < NCELL; c += NWRP) knn_cell(c, lane);
    gsync(sense);

    // -- step 0: layers -------------------------------------------------------
    layer_phase<16, 32, true,  false, false, false, false>(g_x,  sW1, g_ha, nullptr, gtid);
    gsync(sense);
    layer_phase<32, 32, true,  false, false, false, false>(g_ha, sW2, g_hb, nullptr, gtid);
    gsync(sense);
    layer_phase<32, 32, true,  false, true,  false, false>(g_hb, sW3, g_ha, nullptr, gtid); // + zero cnt
    gsync(sense);
    layer_phase<32, 16, false, true,  false, true,  false>(g_ha, sW4, g_x,  nullptr, gtid); // x+=, rebin
    gsync(sense);

    // -- step 1: knn ----------------------------------------------------------
    for (int c = gw; c < NCELL; c += NWRP) knn_cell(c, lane);
    gsync(sense);

    // -- step 1: layers -------------------------------------------------------
    layer_phase<16, 32, true,  false, false, false, false>(g_x,  sW1, g_ha, nullptr, gtid);
    gsync(sense);
    layer_phase<32, 32, true,  false, false, false, false>(g_ha, sW2, g_hb, nullptr, gtid);
    gsync(sense);
    layer_phase<32, 32, true,  false, false, false, false>(g_hb, sW3, g_ha, nullptr, gtid);
    gsync(sense);
    layer_phase<32, 16, false, true,  false, false, true >(g_ha, sW4, g_x,  out, gtid);     // x+=, writeout
}

// ---------------------------------------------------------------------------
extern "C" void kernel_launch(void* const* d_in, const int* in_sizes, int n_in,
                              void* d_out, int out_size) {
    const float* seed = (const float*)d_in[0];
    const float* W1   = (const float*)d_in[1];
    const float* W2   = (const float*)d_in[2];
    const float* W3   = (const float*)d_in[3];
    const float* W4   = (const float*)d_in[4];

    k_fused<<<NBLK, NTHR>>>(seed, W1, W2, W3, W4, (float*)d_out);
}

// round 7
// speedup vs baseline: 1.1776x; 1.1105x over previous
#include <cuda_runtime.h>

// Problem constants
static constexpr int   N_PTS   = 16384;
static constexpr int   C_DIM   = 16;
static constexpr int   H_DIM   = 32;
static constexpr int   KNN     = 9;
static constexpr float UPD_RATE = 1e-4f;

// Spatial grid: 128x128 over [-5,5]; ~16 pts/cell at Gaussian peak.
static constexpr int   GG  = 128;
static constexpr float GB  = 5.0f;
static constexpr int   CAP = 64;
static constexpr float CS  = 2.0f * GB / GG;
static constexpr float INV_CS = GG / (2.0f * GB);
static constexpr int   NCELL = GG * GG;          // 16384

// Scratch (device globals: allocation-free per harness rules)
__device__ __align__(16) float  g_x [N_PTS * C_DIM];
__device__ __align__(16) float  g_ha[N_PTS * H_DIM];
__device__ __align__(16) float  g_hb[N_PTS * H_DIM];
__device__ int    g_idx[N_PTS * KNN];
__device__ int    g_cnt[NCELL];
__device__ float4 g_pts[NCELL * CAP];      // (x, y, bitcast(id), 0)

__device__ __forceinline__ int cell_coord(float v) {
    int c = (int)floorf((v + GB) * INV_CS);
    c = c < 0 ? 0 : c;
    c = c > GG - 1 ? GG - 1 : c;
    return c;
}

__device__ __forceinline__ void bin_insert(float px, float py, int id) {
    int b = cell_coord(py) * GG + cell_coord(px);
    int s = atomicAdd(&g_cnt[b], 1);
    if (s < CAP) g_pts[b * CAP + s] = make_float4(px, py, __int_as_float(id), 0.0f);
}

// ---------------------------------------------------------------------------
// copy seed -> g_x (float4), zero cell counters
__global__ void k_copy_in(const float* __restrict__ src) {
    int i = blockIdx.x * blockDim.x + threadIdx.x;     // 65536 threads
    ((float4*)g_x)[i] = ((const float4*)src)[i];
    if (i < NCELL) g_cnt[i] = 0;
}

__global__ void k_binfill() {
    int i = blockIdx.x * blockDim.x + threadIdx.x;
    if (i >= N_PTS) return;
    bin_insert(g_x[i * C_DIM + 0], g_x[i * C_DIM + 1], i);
}

// ---------------------------------------------------------------------------
// Cell-centric kNN: one warp per grid cell (grid-scheduled small blocks so
// the HW scheduler load-balances dense vs empty cells). Lane = resident
// query; candidates stream via broadcast loads; private sorted top-9 per
// lane; exact per-query box termination; no merge.
__global__ void __launch_bounds__(256) k_knn() {
    int w    = (blockIdx.x * blockDim.x + threadIdx.x) >> 5;
    int lane = threadIdx.x & 31;
    int cell = w;
    if (cell >= NCELL) return;

    int qcnt = g_cnt[cell];
    qcnt = qcnt < CAP ? qcnt : CAP;
    if (qcnt == 0) return;

    const int cx = cell & (GG - 1);
    const int cy = cell >> 7;

    const float INF = __int_as_float(0x7f800000);

    for (int qb = 0; qb < qcnt; qb += 32) {
        int  qi  = qb + lane;
        bool has = (qi < qcnt);
        float4 qp = has ? g_pts[cell * CAP + qi]
                        : make_float4(1e38f, 1e38f, __int_as_float(0), 0.0f);
        const float qx = qp.x;
        const float qy = qp.y;
        const int   q  = __float_as_int(qp.z);

        float bd[KNN];
        int   bi[KNN];
#pragma unroll
        for (int p = 0; p < KNN; ++p) { bd[p] = INF; bi[p] = q; }

        auto stream_cell = [&](int bb, int cc) {
            const float4* pp = &g_pts[bb * CAP];
            for (int t = 0; t < cc; ++t) {
                float4 p = pp[t];                      // broadcast load
                float dx = qx - p.x;
                float dy = qy - p.y;
                float d2 = __fadd_rn(__fmul_rn(dx, dx), __fmul_rn(dy, dy));
                if (d2 < bd[KNN - 1]) {
                    float cd = d2;
                    int   ci = __float_as_int(p.z);
#pragma unroll
                    for (int pos = 0; pos < KNN; ++pos) {
                        if (cd < bd[pos]) {
                            float tf = bd[pos]; bd[pos] = cd; cd = tf;
                            int   ti = bi[pos]; bi[pos] = ci; ci = ti;
                        }
                    }
                }
            }
        };

        stream_cell(cell, qcnt);   // ring 0

        for (int r = 1; r < 2 * GG; ++r) {
            int nc = 8 * r;
            for (int base = 0; base < nc; base += 32) {
                int i = base + lane;
                int b2 = 0, c2 = 0;
                if (i < nc) {
                    int xx, yy;
                    int side = 2 * r + 1;
                    if (i < side)          { xx = cx - r + i;          yy = cy - r; }
                    else if (i < 2 * side) { xx = cx - r + (i - side); yy = cy + r; }
                    else {
                        int j = i - 2 * side;
                        int m = 2 * r - 1;
                        xx = (j < m) ? (cx - r) : (cx + r);
                        yy = cy - r + 1 + (j < m ? j : j - m);
                    }
                    if (xx >= 0 && xx < GG && yy >= 0 && yy < GG) {
                        b2 = yy * GG + xx;
                        c2 = __ldg(&g_cnt[b2]);
                        c2 = c2 < CAP ? c2 : CAP;
                    }
                }
                unsigned mask = __ballot_sync(0xffffffffu, c2 > 0);
                while (mask) {
                    int s = __ffs(mask) - 1;
                    mask &= mask - 1;
                    int bb = __shfl_sync(0xffffffffu, b2, s);
                    int cc = __shfl_sync(0xffffffffu, c2, s);
                    stream_cell(bb, cc);
                }
            }
            // All unscanned points lie outside the scanned box; a query at
            // distance dmin from the box boundary is done once bd[8] <= dmin^2.
            float x_lo = -GB + (float)(cx - r) * CS;
            float x_hi = -GB + (float)(cx + r + 1) * CS;
            float y_lo = -GB + (float)(cy - r) * CS;
            float y_hi = -GB + (float)(cy + r + 1) * CS;
            float dmin = fminf(fminf(qx - x_lo, x_hi - qx),
                               fminf(qy - y_lo, y_hi - qy));
            bool done = (!has) || (dmin > 0.0f && bd[KNN - 1] <= dmin * dmin);
            if (__all_sync(0xffffffffu, done)) break;
        }

        if (has) {
#pragma unroll
            for (int p = 0; p < KNN; ++p) g_idx[q * KNN + p] = bi[p];
        }
    }
}

// ---------------------------------------------------------------------------
// Allgather stage: src[L] -> dst[2L] ordered by the 'hi' bit (static indices).
template <int L>
__device__ __forceinline__ void ag_stage(const float* src, float* dst,
                                         int off, bool hi) {
#pragma unroll
    for (int j = 0; j < L; ++j) {
        float rv = __shfl_xor_sync(0xffffffffu, src[j], off);
        dst[j]     = hi ? rv     : src[j];
        dst[L + j] = hi ? src[j] : rv;
    }
}

// GCN layer: NSUB sub-threads per node (4 for CIN=16, 8 for CIN=32). Each
// sub gathers exactly one float4 per neighbor, allgathers agg via shfl_xor
// stages, then computes its contiguous COUT/NSUB output slice.
template <int CIN, int COUT, int NSUB, bool RELU, bool UPD, bool ZERO,
          bool BINFILL, bool WOUT>
__global__ void __launch_bounds__(256) k_layer(const float* __restrict__ hin,
                                               const float* __restrict__ W,
                                               float* __restrict__ hout,
                                               float* __restrict__ out2) {
    constexpr int CPT = CIN / NSUB;      // = 4
    constexpr int QPT = COUT / NSUB;     // outputs per sub-thread
    static_assert(CPT == 4, "one float4 per neighbor per sub-thread");

    __shared__ float sW[CIN * COUT];
    for (int i = threadIdx.x; i < CIN * COUT; i += blockDim.x) sW[i] = W[i];
    __syncthreads();

    int u = blockIdx.x * blockDim.x + threadIdx.x;   // N_PTS*NSUB units exactly
    if (ZERO && u < NCELL) g_cnt[u] = 0;

    int n   = u / NSUB;
    int sub = u & (NSUB - 1);

    // Gather + mean over my 4-channel slice (9 independent LDG.128).
    float a0[4] = {0.0f, 0.0f, 0.0f, 0.0f};
    const int* ip = g_idx + n * KNN;
#pragma unroll
    for (int k = 0; k < KNN; ++k) {
        int nb = __ldg(&ip[k]);
        float4 v = *(const float4*)(hin + nb * CIN + sub * 4);
        a0[0] += v.x; a0[1] += v.y; a0[2] += v.z; a0[3] += v.w;
    }
#pragma unroll
    for (int c = 0; c < 4; ++c) a0[c] *= (1.0f / 9.0f);

    // Allgather the full CIN-vector across NSUB lanes.
    float full[CIN];
    if constexpr (NSUB == 4) {
        float s1[8];
        ag_stage<4>(a0, s1, 1, (sub & 1) != 0);
        ag_stage<8>(s1, full, 2, (sub & 2) != 0);
    } else {
        float s1[8];
        float s2[16];
        ag_stage<4>(a0, s1, 1, (sub & 1) != 0);
        ag_stage<8>(s1, s2, 2, (sub & 2) != 0);
        ag_stage<16>(s2, full, 4, (sub & 4) != 0);
    }

    // My contiguous output slice.
    const int jbase = sub * QPT;
    float acc[QPT];
#pragma unroll
    for (int j = 0; j < QPT; ++j) acc[j] = 0.0f;
#pragma unroll
    for (int c = 0; c < CIN; ++c) {
        float a = full[c];
        const float* wrow = &sW[c * COUT + jbase];
#pragma unroll
        for (int j = 0; j < QPT; ++j) acc[j] = fmaf(a, wrow[j], acc[j]);
    }

    float* outp = hout + n * COUT + jbase;
    if constexpr (QPT == 2) {
        float2 r = make_float2(acc[0], acc[1]);
        if (RELU) { r.x = fmaxf(r.x, 0.0f); r.y = fmaxf(r.y, 0.0f); }
        if (UPD) {
            float2 old = *(const float2*)outp;
            r.x = fmaf(r.x, UPD_RATE, old.x);
            r.y = fmaf(r.y, UPD_RATE, old.y);
        }
        *(float2*)outp = r;
        if (WOUT) *(float2*)(out2 + n * COUT + jbase) = r;
        if (BINFILL && sub == 0) bin_insert(r.x, r.y, n);
    } else {
#pragma unroll
        for (int v4 = 0; v4 < QPT / 4; ++v4) {
            float4 r;
            r.x = acc[4 * v4 + 0];
            r.y = acc[4 * v4 + 1];
            r.z = acc[4 * v4 + 2];
            r.w = acc[4 * v4 + 3];
            if (RELU) {
                r.x = fmaxf(r.x, 0.0f); r.y = fmaxf(r.y, 0.0f);
                r.z = fmaxf(r.z, 0.0f); r.w = fmaxf(r.w, 0.0f);
            }
            if (UPD) {
                float4 old = ((const float4*)outp)[v4];
                r.x = fmaf(r.x, UPD_RATE, old.x);
                r.y = fmaf(r.y, UPD_RATE, old.y);
                r.z = fmaf(r.z, UPD_RATE, old.z);
                r.w = fmaf(r.w, UPD_RATE, old.w);
            }
            ((float4*)outp)[v4] = r;
            if (WOUT) ((float4*)(out2 + n * COUT + jbase))[v4] = r;
        }
    }
}

// ---------------------------------------------------------------------------
extern "C" void kernel_launch(void* const* d_in, const int* in_sizes, int n_in,
                              void* d_out, int out_size) {
    const float* seed = (const float*)d_in[0];
    const float* W1   = (const float*)d_in[1];
    const float* W2   = (const float*)d_in[2];
    const float* W3   = (const float*)d_in[3];
    const float* W4   = (const float*)d_in[4];
    float* out = (float*)d_out;

    float *px, *pha, *phb;
    cudaGetSymbolAddress((void**)&px,  g_x);
    cudaGetSymbolAddress((void**)&pha, g_ha);
    cudaGetSymbolAddress((void**)&phb, g_hb);

    constexpr int G4 = (N_PTS * 4) / 256;   // 256 blocks (NSUB=4)
    constexpr int G8 = (N_PTS * 8) / 256;   // 512 blocks (NSUB=8)
    constexpr int GK = (NCELL * 32) / 256;  // 2048 blocks, warp per cell

    // step 0
    k_copy_in<<<(N_PTS * C_DIM / 4) / 256, 256>>>(seed);   // + zero counts
    k_binfill<<<N_PTS / 256, 256>>>();
    k_knn<<<GK, 256>>>();
    k_layer<16, 32, 4, true,  false, false, false, false><<<G4, 256>>>(px,  W1, pha, nullptr);
    k_layer<32, 32, 8, true,  false, false, false, false><<<G8, 256>>>(pha, W2, phb, nullptr);
    k_layer<32, 32, 8, true,  false, true,  false, false><<<G8, 256>>>(phb, W3, pha, nullptr); // + zero cnt
    k_layer<32, 16, 8, false, true,  false, true,  false><<<G8, 256>>>(pha, W4, px,  nullptr); // x+=, rebin

    // step 1
    k_knn<<<GK, 256>>>();
    k_layer<16, 32, 4, true,  false, false, false, false><<<G4, 256>>>(px,  W1, pha, nullptr);
    k_layer<32, 32, 8, true,  false, false, false, false><<<G8, 256>>>(pha, W2, phb, nullptr);
    k_layer<32, 32, 8, true,  false, false, false, false><<<G8, 256>>>(phb, W3, pha, nullptr);
    k_layer<32, 16, 8, false, true,  false, false, true ><<<G8, 256>>>(pha, W4, px,  out);     // x+=, writeout
}